// round 5
// baseline (speedup 1.0000x reference)
#include <cuda_runtime.h>
#include <cuda_bf16.h>
#include <math.h>
#include <stdint.h>

#define BATCH 4096
#define DIM   1024
#define EPS_W 0.05f
#define REG_W 0.1f
#define NITER 10
#define INV_B (1.0f/4096.0f)

// GEMM tiling (mma.sync path — tcgen05 is 'a'-gated; this build targets plain sm_103)
#define BM 128
#define BN 128
#define BK 32
#define APAD 8
#define ASTRIDE (BK + APAD)

// Sinkhorn striping
#define STRIPES 256
#define RPS 16                  // rows per stripe

// ---------------- scratch (static device globals; no allocation) ----------------
__device__ __nv_bfloat16 g_an[(size_t)BATCH * DIM];   // 8 MB
__device__ __nv_bfloat16 g_tn[(size_t)BATCH * DIM];   // 8 MB
__device__ __nv_bfloat16 g_Kh[(size_t)BATCH * BATCH]; // 32 MB: M then K in place (bf16)
__device__ float g_part[(size_t)STRIPES * BATCH];     // 4 MB column partials
__device__ float g_u[BATCH];
__device__ float g_v[BATCH];
__device__ float g_col[BATCH];
__device__ float g_ce[BATCH];
__device__ float g_rowsum[BATCH];
__device__ unsigned int g_maxbits;

// ---------------- helpers ----------------
__device__ __forceinline__ uint32_t smem_u32(const void* p) {
    uint32_t a;
    asm("{ .reg .u64 t; cvta.to.shared.u64 t, %1; cvt.u32.u64 %0, t; }" : "=r"(a) : "l"(p));
    return a;
}
__device__ __forceinline__ void cp_async16(uint32_t dst, const void* src) {
    asm volatile("cp.async.cg.shared.global [%0], [%1], 16;" :: "r"(dst), "l"(src));
}
#define CP_COMMIT() asm volatile("cp.async.commit_group;" ::: "memory")
#define CP_WAIT(n)  asm volatile("cp.async.wait_group %0;" :: "n"(n) : "memory")

__device__ __forceinline__ void ldmatrix_x4(uint32_t& r0, uint32_t& r1, uint32_t& r2,
                                            uint32_t& r3, uint32_t addr) {
    asm volatile("ldmatrix.sync.aligned.m8n8.x4.shared.b16 {%0,%1,%2,%3}, [%4];"
                 : "=r"(r0), "=r"(r1), "=r"(r2), "=r"(r3) : "r"(addr));
}
__device__ __forceinline__ void ldmatrix_x2(uint32_t& r0, uint32_t& r1, uint32_t addr) {
    asm volatile("ldmatrix.sync.aligned.m8n8.x2.shared.b16 {%0,%1}, [%2];"
                 : "=r"(r0), "=r"(r1) : "r"(addr));
}
__device__ __forceinline__ void mma_bf16(float& c0, float& c1, float& c2, float& c3,
                                         uint32_t a0, uint32_t a1, uint32_t a2, uint32_t a3,
                                         uint32_t b0, uint32_t b1) {
    asm volatile("mma.sync.aligned.m16n8k16.row.col.f32.bf16.bf16.f32 "
                 "{%0,%1,%2,%3}, {%4,%5,%6,%7}, {%8,%9}, {%0,%1,%2,%3};"
                 : "+f"(c0), "+f"(c1), "+f"(c2), "+f"(c3)
                 : "r"(a0), "r"(a1), "r"(a2), "r"(a3), "r"(b0), "r"(b1));
}

__device__ __forceinline__ float blockReduceSum(float v, float* sh) {
    __syncthreads();
    int lane = threadIdx.x & 31;
    int w    = threadIdx.x >> 5;
    #pragma unroll
    for (int o = 16; o > 0; o >>= 1) v += __shfl_down_sync(0xffffffffu, v, o);
    if (lane == 0) sh[w] = v;
    __syncthreads();
    int nw = blockDim.x >> 5;
    v = (threadIdx.x < nw) ? sh[threadIdx.x] : 0.0f;
    if (w == 0) {
        #pragma unroll
        for (int o = 16; o > 0; o >>= 1) v += __shfl_down_sync(0xffffffffu, v, o);
    }
    if (threadIdx.x == 0) sh[0] = v;
    __syncthreads();
    return sh[0];
}

// ---------------- kernels ----------------

__global__ void init_kernel() {
    int i = blockIdx.x * 256 + threadIdx.x;
    if (i < BATCH) g_u[i] = INV_B;
    if (i == 0) g_maxbits = 0u;
}

__global__ void normalize_kernel(const float* __restrict__ audio,
                                 const float* __restrict__ text) {
    __shared__ float sh[8];
    int row = blockIdx.x;
    const float* src;
    __nv_bfloat16* dst;
    if (row < BATCH) { src = audio + (size_t)row * DIM;           dst = g_an + (size_t)row * DIM; }
    else             { src = text  + (size_t)(row - BATCH) * DIM; dst = g_tn + (size_t)(row - BATCH) * DIM; }
    float4 v = ((const float4*)src)[threadIdx.x];
    float ss = v.x*v.x + v.y*v.y + v.z*v.z + v.w*v.w;
    float tot = blockReduceSum(ss, sh);
    float inv = rsqrtf(tot);
    __nv_bfloat162 h0 = __floats2bfloat162_rn(v.x * inv, v.y * inv);
    __nv_bfloat162 h1 = __floats2bfloat162_rn(v.z * inv, v.w * inv);
    ((__nv_bfloat162*)dst)[2 * threadIdx.x + 0] = h0;
    ((__nv_bfloat162*)dst)[2 * threadIdx.x + 1] = h1;
}

// mma.sync bf16 GEMM: M = 1 - an @ tn^T -> g_Kh (bf16), track global max (fp32 acc).
__global__ void __launch_bounds__(256) gemm_mma_kernel() {
    __shared__ __nv_bfloat16 As[2][BM][ASTRIDE];
    __shared__ __nv_bfloat16 Bs[2][BN][ASTRIDE];
    __shared__ float sred[256];

    int t    = threadIdx.x;
    int wid  = t >> 5;
    int lane = t & 31;
    int warp_m = wid & 1;
    int warp_n = wid >> 1;
    int row0 = blockIdx.y * BM;
    int col0 = blockIdx.x * BN;

    int cid0 = t, cid1 = t + 256;
    int ar0 = cid0 >> 2, ak0 = (cid0 & 3) * 8;
    int ar1 = cid1 >> 2, ak1 = (cid1 & 3) * 8;

    float acc[4][4][4];
    #pragma unroll
    for (int i = 0; i < 4; i++)
        #pragma unroll
        for (int j = 0; j < 4; j++)
            #pragma unroll
            for (int r = 0; r < 4; r++) acc[i][j][r] = 0.0f;

    auto load_stage = [&](int buf, int k0) {
        cp_async16(smem_u32(&As[buf][ar0][ak0]), &g_an[(size_t)(row0 + ar0) * DIM + k0 + ak0]);
        cp_async16(smem_u32(&As[buf][ar1][ak1]), &g_an[(size_t)(row0 + ar1) * DIM + k0 + ak1]);
        cp_async16(smem_u32(&Bs[buf][ar0][ak0]), &g_tn[(size_t)(col0 + ar0) * DIM + k0 + ak0]);
        cp_async16(smem_u32(&Bs[buf][ar1][ak1]), &g_tn[(size_t)(col0 + ar1) * DIM + k0 + ak1]);
        CP_COMMIT();
    };

    load_stage(0, 0);

    const int NK = DIM / BK;
    for (int c = 0; c < NK; c++) {
        int buf = c & 1;
        if (c + 1 < NK) load_stage(buf ^ 1, (c + 1) * BK);
        if (c + 1 < NK) CP_WAIT(1); else CP_WAIT(0);
        __syncthreads();

        #pragma unroll
        for (int kk = 0; kk < BK; kk += 16) {
            uint32_t a[4][4], b[4][2];
            #pragma unroll
            for (int i = 0; i < 4; i++) {
                uint32_t addr = smem_u32(&As[buf][warp_m * 64 + i * 16 + (lane & 15)]
                                            [kk + (lane >> 4) * 8]);
                ldmatrix_x4(a[i][0], a[i][1], a[i][2], a[i][3], addr);
            }
            #pragma unroll
            for (int j = 0; j < 4; j++) {
                uint32_t addr = smem_u32(&Bs[buf][warp_n * 32 + j * 8 + (lane & 7)]
                                            [kk + ((lane >> 3) & 1) * 8]);
                ldmatrix_x2(b[j][0], b[j][1], addr);
            }
            #pragma unroll
            for (int i = 0; i < 4; i++)
                #pragma unroll
                for (int j = 0; j < 4; j++)
                    mma_bf16(acc[i][j][0], acc[i][j][1], acc[i][j][2], acc[i][j][3],
                             a[i][0], a[i][1], a[i][2], a[i][3], b[j][0], b[j][1]);
        }
        __syncthreads();
    }

    float bmax = 0.0f;
    int rr = lane >> 2;
    int cc = (lane & 3) * 2;
    #pragma unroll
    for (int i = 0; i < 4; i++) {
        #pragma unroll
        for (int j = 0; j < 4; j++) {
            float m0 = 1.0f - acc[i][j][0];
            float m1 = 1.0f - acc[i][j][1];
            float m2 = 1.0f - acc[i][j][2];
            float m3 = 1.0f - acc[i][j][3];
            bmax = fmaxf(bmax, fmaxf(fmaxf(m0, m1), fmaxf(m2, m3)));
            int row = row0 + warp_m * 64 + i * 16 + rr;
            int col = col0 + warp_n * 32 + j * 8 + cc;
            *(__nv_bfloat162*)&g_Kh[(size_t)row * BATCH + col]       = __floats2bfloat162_rn(m0, m1);
            *(__nv_bfloat162*)&g_Kh[(size_t)(row + 8) * BATCH + col] = __floats2bfloat162_rn(m2, m3);
        }
    }
    sred[t] = bmax;
    __syncthreads();
    for (int s = 128; s > 0; s >>= 1) {
        if (t < s) sred[t] = fmaxf(sred[t], sred[t + s]);
        __syncthreads();
    }
    if (t == 0) atomicMax(&g_maxbits, __float_as_uint(sred[0]));
}

// K = exp(-M / (eps * maxM)) in place on bf16 (8 values / thread)
__global__ void expk_kernel() {
    size_t i = (size_t)blockIdx.x * 256 + threadIdx.x;   // 0 .. 2097151 uint4 slots
    float mx = __uint_as_float(g_maxbits);
    float s = -1.0f / (EPS_W * mx);
    uint4 q = ((const uint4*)g_Kh)[i];
    __nv_bfloat162* h = reinterpret_cast<__nv_bfloat162*>(&q);
    #pragma unroll
    for (int j = 0; j < 4; j++) {
        float2 f = __bfloat1622float2(h[j]);
        h[j] = __floats2bfloat162_rn(__expf(f.x * s), __expf(f.y * s));
    }
    ((uint4*)g_Kh)[i] = q;
}

// Fused Sinkhorn stripe kernel. 256 blocks x 16 rows, 256 threads.
// DO_ROW: u_r = (1/B)/dot(K[r,:], v)  (warp per 2 rows)
// DO_COL: column partials of sum_r u_r K[r,:] (optionally * v) into g_part
template<bool DO_ROW, bool DO_COL, bool WITHV>
__global__ void __launch_bounds__(256) sink_kernel() {
    __shared__ float s_u[RPS];
    int t = threadIdx.x, wid = t >> 5, lane = t & 31;
    int r0 = blockIdx.x * RPS;

    if (DO_ROW) {
        const float4* v4 = (const float4*)g_v;
        #pragma unroll
        for (int rr = 0; rr < 2; rr++) {
            int r = r0 + wid * 2 + rr;
            const uint4* Krow = (const uint4*)(g_Kh + (size_t)r * BATCH);
            float s = 0.0f;
            #pragma unroll
            for (int i = 0; i < 16; i++) {
                int slot = lane + 32 * i;
                uint4 q = Krow[slot];
                float4 va = v4[slot * 2], vb = v4[slot * 2 + 1];
                __nv_bfloat162* h = reinterpret_cast<__nv_bfloat162*>(&q);
                float2 f0 = __bfloat1622float2(h[0]);
                float2 f1 = __bfloat1622float2(h[1]);
                float2 f2 = __bfloat1622float2(h[2]);
                float2 f3 = __bfloat1622float2(h[3]);
                s += f0.x*va.x + f0.y*va.y + f1.x*va.z + f1.y*va.w
                   + f2.x*vb.x + f2.y*vb.y + f3.x*vb.z + f3.y*vb.w;
            }
            #pragma unroll
            for (int o = 16; o > 0; o >>= 1) s += __shfl_down_sync(0xffffffffu, s, o);
            if (lane == 0) {
                float u = INV_B / s;
                s_u[wid * 2 + rr] = u;
                g_u[r] = u;
            }
        }
        __syncthreads();
    } else if (DO_COL) {
        if (t < RPS) s_u[t] = g_u[r0 + t];
        __syncthreads();
    }

    if (DO_COL) {
        float acc[16];
        #pragma unroll
        for (int j = 0; j < 16; j++) acc[j] = 0.0f;

        for (int r = 0; r < RPS; r++) {
            float ur = s_u[r];
            const uint4* Krow = (const uint4*)(g_Kh + (size_t)(r0 + r) * BATCH);
            #pragma unroll
            for (int k = 0; k < 2; k++) {
                uint4 q = Krow[t + 256 * k];
                __nv_bfloat162* h = reinterpret_cast<__nv_bfloat162*>(&q);
                #pragma unroll
                for (int j = 0; j < 4; j++) {
                    float2 f = __bfloat1622float2(h[j]);
                    acc[k * 8 + j * 2 + 0] += ur * f.x;
                    acc[k * 8 + j * 2 + 1] += ur * f.y;
                }
            }
        }
        float* outp = g_part + (size_t)blockIdx.x * BATCH;
        #pragma unroll
        for (int k = 0; k < 2; k++) {
            int slot = t + 256 * k;
            if (WITHV) {
                const float4* v4 = (const float4*)g_v;
                float4 va = v4[slot * 2], vb = v4[slot * 2 + 1];
                acc[k*8+0] *= va.x; acc[k*8+1] *= va.y; acc[k*8+2] *= va.z; acc[k*8+3] *= va.w;
                acc[k*8+4] *= vb.x; acc[k*8+5] *= vb.y; acc[k*8+6] *= vb.z; acc[k*8+7] *= vb.w;
            }
            ((float4*)outp)[slot * 2 + 0] = make_float4(acc[k*8+0], acc[k*8+1], acc[k*8+2], acc[k*8+3]);
            ((float4*)outp)[slot * 2 + 1] = make_float4(acc[k*8+4], acc[k*8+5], acc[k*8+6], acc[k*8+7]);
        }
    }
}

// reduce the 256 stripe partials. mode 0: v_j=(1/B)/s ; mode 1: col_j=s
__global__ void colreduce_kernel(int mode) {
    int c = blockIdx.x * 256 + threadIdx.x;   // grid 16
    float s = 0.0f;
    #pragma unroll 8
    for (int b = 0; b < STRIPES; b++) s += g_part[(size_t)b * BATCH + c];
    if (mode == 0) g_v[c] = INV_B / s;
    else           g_col[c] = s;
}

// per-row: pi = u_r K[r,:] v ; sum exp(pi), rowsum, diag. ce term = log(se) - pi_rr
__global__ void rowfinal_kernel() {
    __shared__ float sh[4];
    int r = blockIdx.x;
    int t = threadIdx.x;    // 128
    float ur = g_u[r];
    const uint4* Krow = (const uint4*)(g_Kh + (size_t)r * BATCH);
    const float4* v4 = (const float4*)g_v;
    float se = 0.0f, rs = 0.0f;
    #pragma unroll
    for (int i = 0; i < 4; i++) {
        int slot = t + 128 * i;
        uint4 q = Krow[slot];
        float4 va = v4[slot * 2], vb = v4[slot * 2 + 1];
        __nv_bfloat162* h = reinterpret_cast<__nv_bfloat162*>(&q);
        float2 f0 = __bfloat1622float2(h[0]);
        float2 f1 = __bfloat1622float2(h[1]);
        float2 f2 = __bfloat1622float2(h[2]);
        float2 f3 = __bfloat1622float2(h[3]);
        float p0 = ur * f0.x * va.x, p1 = ur * f0.y * va.y;
        float p2 = ur * f1.x * va.z, p3 = ur * f1.y * va.w;
        float p4 = ur * f2.x * vb.x, p5 = ur * f2.y * vb.y;
        float p6 = ur * f3.x * vb.z, p7 = ur * f3.y * vb.w;
        se += __expf(p0) + __expf(p1) + __expf(p2) + __expf(p3)
            + __expf(p4) + __expf(p5) + __expf(p6) + __expf(p7);
        rs += p0 + p1 + p2 + p3 + p4 + p5 + p6 + p7;
    }
    float se_t = blockReduceSum(se, sh);
    float rs_t = blockReduceSum(rs, sh);
    if (t == 0) {
        float kd = __bfloat162float(g_Kh[(size_t)r * BATCH + r]);
        float diag = ur * kd * g_v[r];
        g_ce[r] = logf(se_t) - diag;
        g_rowsum[r] = rs_t;
    }
}

__global__ void final_kernel(float* __restrict__ out) {
    __shared__ float sh[8];
    int t = threadIdx.x;   // 256
    float ce = 0.0f, klr = 0.0f, klc = 0.0f;
    for (int i = t; i < BATCH; i += 256) {
        ce += g_ce[i];
        float rs = g_rowsum[i];
        klr += rs * (logf(rs) - INV_B);
        float cs = g_col[i];
        klc += cs * (logf(cs) - INV_B);
    }
    float ce_t  = blockReduceSum(ce,  sh);
    float klr_t = blockReduceSum(klr, sh);
    float klc_t = blockReduceSum(klc, sh);
    if (t == 0)
        out[0] = ce_t * INV_B + REG_W * (klc_t * INV_B + klr_t * INV_B);
}

// ---------------- launcher ----------------
extern "C" void kernel_launch(void* const* d_in, const int* in_sizes, int n_in,
                              void* d_out, int out_size) {
    const float* audio = (const float*)d_in[0];
    const float* text  = (const float*)d_in[1];
    float* out = (float*)d_out;

    init_kernel<<<16, 256>>>();
    normalize_kernel<<<2 * BATCH, 256>>>(audio, text);
    gemm_mma_kernel<<<dim3(BATCH / BN, BATCH / BM), 256>>>();
    expk_kernel<<<8192, 256>>>();

    // v1 = b / (K^T u0)
    sink_kernel<false, true, false><<<STRIPES, 256>>>();
    colreduce_kernel<<<16, 256>>>(0);
    // 9 x fused: u_t = a/(K v_t) ; partials(u_t) -> v_{t+1}
    for (int it = 0; it < NITER - 1; it++) {
        sink_kernel<true, true, false><<<STRIPES, 256>>>();
        colreduce_kernel<<<16, 256>>>(0);
    }
    // u10 = a/(K v10)
    sink_kernel<true, false, false><<<STRIPES, 256>>>();

    // column sums of pi, then row stats + combine
    sink_kernel<false, true, true><<<STRIPES, 256>>>();
    colreduce_kernel<<<16, 256>>>(1);
    rowfinal_kernel<<<BATCH, 128>>>();
    final_kernel<<<1, 256>>>(out);
}

// round 7
// speedup vs baseline: 1.3703x; 1.3703x over previous
#include <cuda_runtime.h>
#include <cuda_bf16.h>
#include <math.h>
#include <stdint.h>

#define BATCH 4096
#define DIM   1024
#define EPS_W 0.05f
#define REG_W 0.1f
#define NITER 10
#define INV_B (1.0f/4096.0f)

// GEMM tiling (mma.sync path — tcgen05 is 'a'-gated; this build targets plain sm_103)
#define BM 128
#define BN 128
#define BK 32
#define APAD 8
#define ASTRIDE (BK + APAD)

// persistent Sinkhorn
#define NB 256                  // blocks (co-resident: launch_bounds(512,2) -> 296 capacity)
#define NT 512                  // threads per block
#define RPB 16                  // rows per block
#define CPB 16                  // cols per block in v-reduce

// ---------------- scratch (static device globals; no allocation) ----------------
__device__ __nv_bfloat16 g_an[(size_t)BATCH * DIM];   // 8 MB
__device__ __nv_bfloat16 g_tn[(size_t)BATCH * DIM];   // 8 MB
__device__ __nv_bfloat16 g_Kh[(size_t)BATCH * BATCH]; // 32 MB: M then K in place (bf16)
__device__ float g_part[(size_t)NB * BATCH];          // 4 MB partials [block][col]
__device__ float g_v[BATCH];
__device__ float g_col[BATCH];
__device__ float g_ce[BATCH];
__device__ float g_rowsum[BATCH];
__device__ unsigned int g_maxbits;
__device__ unsigned int g_barcnt;
__device__ unsigned int g_barsense;

// ---------------- helpers ----------------
__device__ __forceinline__ uint32_t smem_u32(const void* p) {
    uint32_t a;
    asm("{ .reg .u64 t; cvta.to.shared.u64 t, %1; cvt.u32.u64 %0, t; }" : "=r"(a) : "l"(p));
    return a;
}
__device__ __forceinline__ void cp_async16(uint32_t dst, const void* src) {
    asm volatile("cp.async.cg.shared.global [%0], [%1], 16;" :: "r"(dst), "l"(src));
}
#define CP_COMMIT() asm volatile("cp.async.commit_group;" ::: "memory")
#define CP_WAIT(n)  asm volatile("cp.async.wait_group %0;" :: "n"(n) : "memory")

__device__ __forceinline__ void ldmatrix_x4(uint32_t& r0, uint32_t& r1, uint32_t& r2,
                                            uint32_t& r3, uint32_t addr) {
    asm volatile("ldmatrix.sync.aligned.m8n8.x4.shared.b16 {%0,%1,%2,%3}, [%4];"
                 : "=r"(r0), "=r"(r1), "=r"(r2), "=r"(r3) : "r"(addr));
}
__device__ __forceinline__ void ldmatrix_x2(uint32_t& r0, uint32_t& r1, uint32_t addr) {
    asm volatile("ldmatrix.sync.aligned.m8n8.x2.shared.b16 {%0,%1}, [%2];"
                 : "=r"(r0), "=r"(r1) : "r"(addr));
}
__device__ __forceinline__ void mma_bf16(float& c0, float& c1, float& c2, float& c3,
                                         uint32_t a0, uint32_t a1, uint32_t a2, uint32_t a3,
                                         uint32_t b0, uint32_t b1) {
    asm volatile("mma.sync.aligned.m16n8k16.row.col.f32.bf16.bf16.f32 "
                 "{%0,%1,%2,%3}, {%4,%5,%6,%7}, {%8,%9}, {%0,%1,%2,%3};"
                 : "+f"(c0), "+f"(c1), "+f"(c2), "+f"(c3)
                 : "r"(a0), "r"(a1), "r"(a2), "r"(a3), "r"(b0), "r"(b1));
}

__device__ __forceinline__ float blockReduceSum512(float v, float* sh) {
    __syncthreads();
    int lane = threadIdx.x & 31;
    int w    = threadIdx.x >> 5;
    #pragma unroll
    for (int o = 16; o > 0; o >>= 1) v += __shfl_down_sync(0xffffffffu, v, o);
    if (lane == 0) sh[w] = v;
    __syncthreads();
    v = (threadIdx.x < 16) ? sh[threadIdx.x] : 0.0f;
    if (w == 0) {
        #pragma unroll
        for (int o = 8; o > 0; o >>= 1) v += __shfl_down_sync(0xffffffffu, v, o);
    }
    if (threadIdx.x == 0) sh[0] = v;
    __syncthreads();
    return sh[0];
}

// ---------------- kernels ----------------

__global__ void init_kernel() {
    if (threadIdx.x == 0) {
        g_maxbits = 0u;
        g_barcnt = 0u;
        g_barsense = 0u;
    }
}

__global__ void normalize_kernel(const float* __restrict__ audio,
                                 const float* __restrict__ text) {
    __shared__ float sh[8];
    int row = blockIdx.x;
    const float* src;
    __nv_bfloat16* dst;
    if (row < BATCH) { src = audio + (size_t)row * DIM;           dst = g_an + (size_t)row * DIM; }
    else             { src = text  + (size_t)(row - BATCH) * DIM; dst = g_tn + (size_t)(row - BATCH) * DIM; }
    float4 v = ((const float4*)src)[threadIdx.x];
    float ss = v.x*v.x + v.y*v.y + v.z*v.z + v.w*v.w;
    // 256-thread block reduce
    int lane = threadIdx.x & 31, w = threadIdx.x >> 5;
    #pragma unroll
    for (int o = 16; o > 0; o >>= 1) ss += __shfl_down_sync(0xffffffffu, ss, o);
    if (lane == 0) sh[w] = ss;
    __syncthreads();
    float tot = 0.0f;
    if (threadIdx.x < 8) tot = sh[threadIdx.x];
    if (w == 0) {
        #pragma unroll
        for (int o = 4; o > 0; o >>= 1) tot += __shfl_down_sync(0xffffffffu, tot, o);
        if (lane == 0) sh[0] = tot;
    }
    __syncthreads();
    float inv = rsqrtf(sh[0]);
    __nv_bfloat162 h0 = __floats2bfloat162_rn(v.x * inv, v.y * inv);
    __nv_bfloat162 h1 = __floats2bfloat162_rn(v.z * inv, v.w * inv);
    ((__nv_bfloat162*)dst)[2 * threadIdx.x + 0] = h0;
    ((__nv_bfloat162*)dst)[2 * threadIdx.x + 1] = h1;
}

// mma.sync bf16 GEMM: M = 1 - an @ tn^T -> g_Kh (bf16), track global max.
__global__ void __launch_bounds__(256) gemm_mma_kernel() {
    __shared__ __nv_bfloat16 As[2][BM][ASTRIDE];
    __shared__ __nv_bfloat16 Bs[2][BN][ASTRIDE];
    __shared__ float sred[256];

    int t    = threadIdx.x;
    int wid  = t >> 5;
    int lane = t & 31;
    int warp_m = wid & 1;
    int warp_n = wid >> 1;
    int row0 = blockIdx.y * BM;
    int col0 = blockIdx.x * BN;

    int cid0 = t, cid1 = t + 256;
    int ar0 = cid0 >> 2, ak0 = (cid0 & 3) * 8;
    int ar1 = cid1 >> 2, ak1 = (cid1 & 3) * 8;

    float acc[4][4][4];
    #pragma unroll
    for (int i = 0; i < 4; i++)
        #pragma unroll
        for (int j = 0; j < 4; j++)
            #pragma unroll
            for (int r = 0; r < 4; r++) acc[i][j][r] = 0.0f;

    auto load_stage = [&](int buf, int k0) {
        cp_async16(smem_u32(&As[buf][ar0][ak0]), &g_an[(size_t)(row0 + ar0) * DIM + k0 + ak0]);
        cp_async16(smem_u32(&As[buf][ar1][ak1]), &g_an[(size_t)(row0 + ar1) * DIM + k0 + ak1]);
        cp_async16(smem_u32(&Bs[buf][ar0][ak0]), &g_tn[(size_t)(col0 + ar0) * DIM + k0 + ak0]);
        cp_async16(smem_u32(&Bs[buf][ar1][ak1]), &g_tn[(size_t)(col0 + ar1) * DIM + k0 + ak1]);
        CP_COMMIT();
    };

    load_stage(0, 0);

    const int NK = DIM / BK;
    for (int c = 0; c < NK; c++) {
        int buf = c & 1;
        if (c + 1 < NK) load_stage(buf ^ 1, (c + 1) * BK);
        if (c + 1 < NK) CP_WAIT(1); else CP_WAIT(0);
        __syncthreads();

        #pragma unroll
        for (int kk = 0; kk < BK; kk += 16) {
            uint32_t a[4][4], b[4][2];
            #pragma unroll
            for (int i = 0; i < 4; i++) {
                uint32_t addr = smem_u32(&As[buf][warp_m * 64 + i * 16 + (lane & 15)]
                                            [kk + (lane >> 4) * 8]);
                ldmatrix_x4(a[i][0], a[i][1], a[i][2], a[i][3], addr);
            }
            #pragma unroll
            for (int j = 0; j < 4; j++) {
                uint32_t addr = smem_u32(&Bs[buf][warp_n * 32 + j * 8 + (lane & 7)]
                                            [kk + ((lane >> 3) & 1) * 8]);
                ldmatrix_x2(b[j][0], b[j][1], addr);
            }
            #pragma unroll
            for (int i = 0; i < 4; i++)
                #pragma unroll
                for (int j = 0; j < 4; j++)
                    mma_bf16(acc[i][j][0], acc[i][j][1], acc[i][j][2], acc[i][j][3],
                             a[i][0], a[i][1], a[i][2], a[i][3], b[j][0], b[j][1]);
        }
        __syncthreads();
    }

    float bmax = 0.0f;
    int rr = lane >> 2;
    int cc = (lane & 3) * 2;
    #pragma unroll
    for (int i = 0; i < 4; i++) {
        #pragma unroll
        for (int j = 0; j < 4; j++) {
            float m0 = 1.0f - acc[i][j][0];
            float m1 = 1.0f - acc[i][j][1];
            float m2 = 1.0f - acc[i][j][2];
            float m3 = 1.0f - acc[i][j][3];
            bmax = fmaxf(bmax, fmaxf(fmaxf(m0, m1), fmaxf(m2, m3)));
            int row = row0 + warp_m * 64 + i * 16 + rr;
            int col = col0 + warp_n * 32 + j * 8 + cc;
            *(__nv_bfloat162*)&g_Kh[(size_t)row * BATCH + col]       = __floats2bfloat162_rn(m0, m1);
            *(__nv_bfloat162*)&g_Kh[(size_t)(row + 8) * BATCH + col] = __floats2bfloat162_rn(m2, m3);
        }
    }
    sred[t] = bmax;
    __syncthreads();
    for (int s = 128; s > 0; s >>= 1) {
        if (t < s) sred[t] = fmaxf(sred[t], sred[t + s]);
        __syncthreads();
    }
    if (t == 0) atomicMax(&g_maxbits, __float_as_uint(sred[0]));
}

// ---------------- persistent Sinkhorn ----------------

struct SinkShared {
    float u[RPB];
    unsigned int sense;
    float red[32][CPB];
    float sh[16];
};

__device__ __forceinline__ void grid_bar(SinkShared* S) {
    __threadfence();
    __syncthreads();
    if (threadIdx.x == 0) {
        unsigned int target = S->sense ^ 1u;
        S->sense = target;
        unsigned int old = atomicAdd(&g_barcnt, 1u);
        if (old == NB - 1u) {
            g_barcnt = 0u;
            __threadfence();
            atomicExch(&g_barsense, target);
        } else {
            while (atomicAdd(&g_barsense, 0u) != target) { }
        }
        __threadfence();
    }
    __syncthreads();
}

// col partials for this block's 16-row stripe: part[b][j] = sum_r u_r K[r][j]
template<bool FIRST>
__device__ __forceinline__ void phaseA(SinkShared* S, int b, int r0, float sc) {
    int t = threadIdx.x;
    float acc[8];
    #pragma unroll
    for (int j = 0; j < 8; j++) acc[j] = 0.0f;

    #pragma unroll 4
    for (int r = 0; r < RPB; r++) {
        uint4* row = (uint4*)(g_Kh + (size_t)(r0 + r) * BATCH);
        uint4 q = row[t];
        __nv_bfloat162* h = reinterpret_cast<__nv_bfloat162*>(&q);
        float f[8];
        #pragma unroll
        for (int j = 0; j < 4; j++) {
            float2 p = __bfloat1622float2(h[j]);
            f[2*j] = p.x; f[2*j+1] = p.y;
        }
        if (FIRST) {
            // fused: K = exp(M * sc); write back, accumulate with u = INV_B
            #pragma unroll
            for (int j = 0; j < 8; j++) f[j] = __expf(f[j] * sc);
            #pragma unroll
            for (int j = 0; j < 4; j++)
                h[j] = __floats2bfloat162_rn(f[2*j], f[2*j+1]);
            row[t] = q;
            #pragma unroll
            for (int j = 0; j < 8; j++) acc[j] += f[j];
        } else {
            float ur = S->u[r];
            #pragma unroll
            for (int j = 0; j < 8; j++) acc[j] += ur * f[j];
        }
    }
    if (FIRST) {
        #pragma unroll
        for (int j = 0; j < 8; j++) acc[j] *= INV_B;
    }
    float4* pp = (float4*)(g_part + (size_t)b * BATCH);
    pp[2*t + 0] = make_float4(acc[0], acc[1], acc[2], acc[3]);
    pp[2*t + 1] = make_float4(acc[4], acc[5], acc[6], acc[7]);
}

// reduce partials for this block's 16 cols. MODE 0: v = INV_B/s ; MODE 1: col = s*v
template<int MODE>
__device__ __forceinline__ void phaseB(SinkShared* S, int b) {
    int t = threadIdx.x;
    int c0 = b * CPB;
    int p  = t >> 4;        // 0..31
    int cl = t & 15;
    float s = 0.0f;
    #pragma unroll
    for (int i = 0; i < 8; i++)
        s += g_part[(size_t)(p + 32 * i) * BATCH + c0 + cl];
    S->red[p][cl] = s;
    __syncthreads();
    if (t < CPB) {
        float s2 = 0.0f;
        #pragma unroll
        for (int g = 0; g < 32; g++) s2 += S->red[g][t];
        if (MODE == 0) g_v[c0 + t] = INV_B / s2;
        else           g_col[c0 + t] = s2 * g_v[c0 + t];
    }
    __syncthreads();
}

// row dots: u_r = INV_B / dot(K[r,:], v) ; warp per row
__device__ __forceinline__ void phaseC(SinkShared* S, int r0) {
    int warp = threadIdx.x >> 5, lane = threadIdx.x & 31;
    const uint4* row = (const uint4*)(g_Kh + (size_t)(r0 + warp) * BATCH);
    const float4* v4 = (const float4*)g_v;
    float s = 0.0f;
    #pragma unroll
    for (int i = 0; i < 16; i++) {
        int slot = lane + 32 * i;
        uint4 q = row[slot];
        float4 va = v4[2*slot], vb = v4[2*slot + 1];
        __nv_bfloat162* h = reinterpret_cast<__nv_bfloat162*>(&q);
        float2 f0 = __bfloat1622float2(h[0]);
        float2 f1 = __bfloat1622float2(h[1]);
        float2 f2 = __bfloat1622float2(h[2]);
        float2 f3 = __bfloat1622float2(h[3]);
        s += f0.x*va.x + f0.y*va.y + f1.x*va.z + f1.y*va.w
           + f2.x*vb.x + f2.y*vb.y + f3.x*vb.z + f3.y*vb.w;
    }
    #pragma unroll
    for (int o = 16; o > 0; o >>= 1) s += __shfl_down_sync(0xffffffffu, s, o);
    if (lane == 0) S->u[warp] = INV_B / s;
    __syncthreads();
}

// row stats: se = sum exp(pi), rs = sum pi, ce = log(se) - pi_rr
__device__ __forceinline__ void phaseR(SinkShared* S, int r0) {
    int warp = threadIdx.x >> 5, lane = threadIdx.x & 31;
    int r = r0 + warp;
    float ur = S->u[warp];
    const uint4* row = (const uint4*)(g_Kh + (size_t)r * BATCH);
    const float4* v4 = (const float4*)g_v;
    float se = 0.0f, rs = 0.0f;
    #pragma unroll
    for (int i = 0; i < 16; i++) {
        int slot = lane + 32 * i;
        uint4 q = row[slot];
        float4 va = v4[2*slot], vb = v4[2*slot + 1];
        __nv_bfloat162* h = reinterpret_cast<__nv_bfloat162*>(&q);
        float2 f0 = __bfloat1622float2(h[0]);
        float2 f1 = __bfloat1622float2(h[1]);
        float2 f2 = __bfloat1622float2(h[2]);
        float2 f3 = __bfloat1622float2(h[3]);
        float p0 = ur * f0.x * va.x, p1 = ur * f0.y * va.y;
        float p2 = ur * f1.x * va.z, p3 = ur * f1.y * va.w;
        float p4 = ur * f2.x * vb.x, p5 = ur * f2.y * vb.y;
        float p6 = ur * f3.x * vb.z, p7 = ur * f3.y * vb.w;
        se += __expf(p0) + __expf(p1) + __expf(p2) + __expf(p3)
            + __expf(p4) + __expf(p5) + __expf(p6) + __expf(p7);
        rs += p0 + p1 + p2 + p3 + p4 + p5 + p6 + p7;
    }
    #pragma unroll
    for (int o = 16; o > 0; o >>= 1) {
        se += __shfl_down_sync(0xffffffffu, se, o);
        rs += __shfl_down_sync(0xffffffffu, rs, o);
    }
    if (lane == 0) {
        float kd = __bfloat162float(g_Kh[(size_t)r * BATCH + r]);
        float diag = ur * kd * g_v[r];
        g_ce[r] = logf(se) - diag;
        g_rowsum[r] = rs;
    }
}

__global__ void __launch_bounds__(NT, 2) sink_persist_kernel(float* __restrict__ out) {
    __shared__ SinkShared S;
    int b = blockIdx.x;
    int t = threadIdx.x;
    int r0 = b * RPB;

    if (t == 0) S.sense = 0u;
    __syncthreads();

    float mx = __uint_as_float(g_maxbits);
    float sc = -1.0f / (EPS_W * mx);

    // iteration 0: exp fusion + col partials (u = INV_B), then v1
    phaseA<true>(&S, b, r0, sc);
    grid_bar(&S);
    phaseB<0>(&S, b);
    grid_bar(&S);

    // iterations 1..9
    for (int it = 1; it < NITER; it++) {
        phaseC(&S, r0);            // u_it from v_it
        phaseA<false>(&S, b, r0, sc);
        grid_bar(&S);
        phaseB<0>(&S, b);          // v_{it+1}
        grid_bar(&S);
    }

    phaseC(&S, r0);                // u_10 from v_10
    phaseA<false>(&S, b, r0, sc);  // partials with u_10
    grid_bar(&S);
    phaseB<1>(&S, b);              // g_col = colsum(pi)
    phaseR(&S, r0);                // row stats
    grid_bar(&S);

    if (b == 0) {
        float ce = 0.0f, klr = 0.0f, klc = 0.0f;
        for (int i = t; i < BATCH; i += NT) {
            ce += g_ce[i];
            float rs = g_rowsum[i];
            klr += rs * (logf(rs) - INV_B);
            float cs = g_col[i];
            klc += cs * (logf(cs) - INV_B);
        }
        float ce_t  = blockReduceSum512(ce,  S.sh);
        float klr_t = blockReduceSum512(klr, S.sh);
        float klc_t = blockReduceSum512(klc, S.sh);
        if (t == 0)
            out[0] = ce_t * INV_B + REG_W * (klc_t * INV_B + klr_t * INV_B);
    }
}

// ---------------- launcher ----------------
extern "C" void kernel_launch(void* const* d_in, const int* in_sizes, int n_in,
                              void* d_out, int out_size) {
    const float* audio = (const float*)d_in[0];
    const float* text  = (const float*)d_in[1];
    float* out = (float*)d_out;

    init_kernel<<<1, 32>>>();
    normalize_kernel<<<2 * BATCH, 256>>>(audio, text);
    gemm_mma_kernel<<<dim3(BATCH / BN, BATCH / BM), 256>>>();
    sink_persist_kernel<<<NB, NT>>>(out);
}

// round 8
// speedup vs baseline: 1.3978x; 1.0201x over previous
#include <cuda_runtime.h>
#include <cuda_bf16.h>
#include <math.h>
#include <stdint.h>

#define BATCH 4096
#define DIM   1024
#define EPS_W 0.05f
#define REG_W 0.1f
#define NITER 10
#define INV_B (1.0f/4096.0f)

// GEMM tiling (mma.sync path — tcgen05 is 'a'-gated; this build targets plain sm_103)
#define BM 128
#define BN 128
#define BK 32
#define APAD 8
#define ASTRIDE (BK + APAD)
#define STAGES 4
#define GEMM_SMEM (STAGES * (BM + BN) * ASTRIDE * 2)   // 81920 bytes

// persistent Sinkhorn
#define NB 256
#define NT 512
#define RPB 16
#define CPB 16

// ---------------- scratch (static device globals; no allocation) ----------------
__device__ __nv_bfloat16 g_an[(size_t)BATCH * DIM];   // 8 MB
__device__ __nv_bfloat16 g_tn[(size_t)BATCH * DIM];   // 8 MB
__device__ __nv_bfloat16 g_Kh[(size_t)BATCH * BATCH]; // 32 MB: M then K in place (bf16)
__device__ float g_part[(size_t)NB * BATCH];          // 4 MB partials [block][col]
__device__ float g_v[BATCH];
__device__ float g_col[BATCH];
__device__ float g_ce[BATCH];
__device__ float g_rowsum[BATCH];
__device__ unsigned int g_maxbits;
__device__ unsigned int g_barcnt;
__device__ unsigned int g_barsense;

// ---------------- helpers ----------------
__device__ __forceinline__ uint32_t smem_u32(const void* p) {
    uint32_t a;
    asm("{ .reg .u64 t; cvta.to.shared.u64 t, %1; cvt.u32.u64 %0, t; }" : "=r"(a) : "l"(p));
    return a;
}
__device__ __forceinline__ void cp_async16(uint32_t dst, const void* src) {
    asm volatile("cp.async.cg.shared.global [%0], [%1], 16;" :: "r"(dst), "l"(src));
}
#define CP_COMMIT() asm volatile("cp.async.commit_group;" ::: "memory")
#define CP_WAIT(n)  asm volatile("cp.async.wait_group %0;" :: "n"(n) : "memory")

__device__ __forceinline__ void ldmatrix_x4(uint32_t& r0, uint32_t& r1, uint32_t& r2,
                                            uint32_t& r3, uint32_t addr) {
    asm volatile("ldmatrix.sync.aligned.m8n8.x4.shared.b16 {%0,%1,%2,%3}, [%4];"
                 : "=r"(r0), "=r"(r1), "=r"(r2), "=r"(r3) : "r"(addr));
}
__device__ __forceinline__ void mma_bf16(float& c0, float& c1, float& c2, float& c3,
                                         uint32_t a0, uint32_t a1, uint32_t a2, uint32_t a3,
                                         uint32_t b0, uint32_t b1) {
    asm volatile("mma.sync.aligned.m16n8k16.row.col.f32.bf16.bf16.f32 "
                 "{%0,%1,%2,%3}, {%4,%5,%6,%7}, {%8,%9}, {%0,%1,%2,%3};"
                 : "+f"(c0), "+f"(c1), "+f"(c2), "+f"(c3)
                 : "r"(a0), "r"(a1), "r"(a2), "r"(a3), "r"(b0), "r"(b1));
}
__device__ __forceinline__ unsigned ld_acquire(unsigned* p) {
    unsigned v;
    asm volatile("ld.acquire.gpu.global.u32 %0, [%1];" : "=r"(v) : "l"(p) : "memory");
    return v;
}
__device__ __forceinline__ void st_release(unsigned* p, unsigned v) {
    asm volatile("st.release.gpu.global.u32 [%0], %1;" :: "l"(p), "r"(v) : "memory");
}

__device__ __forceinline__ float blockReduceSum512(float v, float* sh) {
    __syncthreads();
    int lane = threadIdx.x & 31;
    int w    = threadIdx.x >> 5;
    #pragma unroll
    for (int o = 16; o > 0; o >>= 1) v += __shfl_down_sync(0xffffffffu, v, o);
    if (lane == 0) sh[w] = v;
    __syncthreads();
    v = (threadIdx.x < 16) ? sh[threadIdx.x] : 0.0f;
    if (w == 0) {
        #pragma unroll
        for (int o = 8; o > 0; o >>= 1) v += __shfl_down_sync(0xffffffffu, v, o);
    }
    if (threadIdx.x == 0) sh[0] = v;
    __syncthreads();
    return sh[0];
}

// ---------------- kernels ----------------

__global__ void init_kernel() {
    if (threadIdx.x == 0) {
        g_maxbits = 0u;
        g_barcnt = 0u;
        g_barsense = 0u;
    }
}

__global__ void normalize_kernel(const float* __restrict__ audio,
                                 const float* __restrict__ text) {
    __shared__ float sh[8];
    int row = blockIdx.x;
    const float* src;
    __nv_bfloat16* dst;
    if (row < BATCH) { src = audio + (size_t)row * DIM;           dst = g_an + (size_t)row * DIM; }
    else             { src = text  + (size_t)(row - BATCH) * DIM; dst = g_tn + (size_t)(row - BATCH) * DIM; }
    float4 v = ((const float4*)src)[threadIdx.x];
    float ss = v.x*v.x + v.y*v.y + v.z*v.z + v.w*v.w;
    int lane = threadIdx.x & 31, w = threadIdx.x >> 5;
    #pragma unroll
    for (int o = 16; o > 0; o >>= 1) ss += __shfl_down_sync(0xffffffffu, ss, o);
    if (lane == 0) sh[w] = ss;
    __syncthreads();
    float tot = 0.0f;
    if (threadIdx.x < 8) tot = sh[threadIdx.x];
    if (w == 0) {
        #pragma unroll
        for (int o = 4; o > 0; o >>= 1) tot += __shfl_down_sync(0xffffffffu, tot, o);
        if (lane == 0) sh[0] = tot;
    }
    __syncthreads();
    float inv = rsqrtf(sh[0]);
    __nv_bfloat162 h0 = __floats2bfloat162_rn(v.x * inv, v.y * inv);
    __nv_bfloat162 h1 = __floats2bfloat162_rn(v.z * inv, v.w * inv);
    ((__nv_bfloat162*)dst)[2 * threadIdx.x + 0] = h0;
    ((__nv_bfloat162*)dst)[2 * threadIdx.x + 1] = h1;
}

// mma.sync bf16 GEMM: M = 1 - an @ tn^T -> g_Kh (bf16), track global max.
// 4-stage cp.async pipeline, 1 syncthreads/chunk, dynamic smem.
__global__ void __launch_bounds__(256, 2) gemm_mma_kernel() {
    extern __shared__ char gsm[];
    typedef __nv_bfloat16 TileA[BM][ASTRIDE];
    typedef __nv_bfloat16 TileB[BN][ASTRIDE];
    TileA* As = (TileA*)gsm;
    TileB* Bs = (TileB*)(gsm + STAGES * BM * ASTRIDE * 2);
    __shared__ float sred[256];

    int t    = threadIdx.x;
    int wid  = t >> 5;
    int lane = t & 31;
    int warp_m = wid & 1;
    int warp_n = wid >> 1;
    int row0 = blockIdx.y * BM;
    int col0 = blockIdx.x * BN;

    int cid0 = t, cid1 = t + 256;
    int ar0 = cid0 >> 2, ak0 = (cid0 & 3) * 8;
    int ar1 = cid1 >> 2, ak1 = (cid1 & 3) * 8;

    float acc[4][4][4];
    #pragma unroll
    for (int i = 0; i < 4; i++)
        #pragma unroll
        for (int j = 0; j < 4; j++)
            #pragma unroll
            for (int r = 0; r < 4; r++) acc[i][j][r] = 0.0f;

    auto load_stage = [&](int s, int k0) {
        cp_async16(smem_u32(&As[s][ar0][ak0]), &g_an[(size_t)(row0 + ar0) * DIM + k0 + ak0]);
        cp_async16(smem_u32(&As[s][ar1][ak1]), &g_an[(size_t)(row0 + ar1) * DIM + k0 + ak1]);
        cp_async16(smem_u32(&Bs[s][ar0][ak0]), &g_tn[(size_t)(col0 + ar0) * DIM + k0 + ak0]);
        cp_async16(smem_u32(&Bs[s][ar1][ak1]), &g_tn[(size_t)(col0 + ar1) * DIM + k0 + ak1]);
        CP_COMMIT();
    };

    load_stage(0, 0);
    load_stage(1, BK);
    load_stage(2, 2 * BK);

    const int NK = DIM / BK;   // 32
    for (int c = 0; c < NK; c++) {
        int buf = c & 3;
        CP_WAIT(2);
        __syncthreads();
        if (c + 3 < NK) load_stage((c + 3) & 3, (c + 3) * BK);
        else            CP_COMMIT();           // empty group keeps wait counts uniform

        #pragma unroll
        for (int kk = 0; kk < BK; kk += 16) {
            uint32_t a[4][4], b[4][2];
            #pragma unroll
            for (int i = 0; i < 4; i++) {
                uint32_t addr = smem_u32(&As[buf][warp_m * 64 + i * 16 + (lane & 15)]
                                            [kk + (lane >> 4) * 8]);
                ldmatrix_x4(a[i][0], a[i][1], a[i][2], a[i][3], addr);
            }
            #pragma unroll
            for (int j = 0; j < 4; j += 2) {
                uint32_t addr = smem_u32(&Bs[buf][warp_n * 32 + j * 8 + (lane >> 4) * 8 + (lane & 7)]
                                            [kk + ((lane >> 3) & 1) * 8]);
                ldmatrix_x4(b[j][0], b[j][1], b[j+1][0], b[j+1][1], addr);
            }
            #pragma unroll
            for (int i = 0; i < 4; i++)
                #pragma unroll
                for (int j = 0; j < 4; j++)
                    mma_bf16(acc[i][j][0], acc[i][j][1], acc[i][j][2], acc[i][j][3],
                             a[i][0], a[i][1], a[i][2], a[i][3], b[j][0], b[j][1]);
        }
    }

    float bmax = 0.0f;
    int rr = lane >> 2;
    int cc = (lane & 3) * 2;
    #pragma unroll
    for (int i = 0; i < 4; i++) {
        #pragma unroll
        for (int j = 0; j < 4; j++) {
            float m0 = 1.0f - acc[i][j][0];
            float m1 = 1.0f - acc[i][j][1];
            float m2 = 1.0f - acc[i][j][2];
            float m3 = 1.0f - acc[i][j][3];
            bmax = fmaxf(bmax, fmaxf(fmaxf(m0, m1), fmaxf(m2, m3)));
            int row = row0 + warp_m * 64 + i * 16 + rr;
            int col = col0 + warp_n * 32 + j * 8 + cc;
            *(__nv_bfloat162*)&g_Kh[(size_t)row * BATCH + col]       = __floats2bfloat162_rn(m0, m1);
            *(__nv_bfloat162*)&g_Kh[(size_t)(row + 8) * BATCH + col] = __floats2bfloat162_rn(m2, m3);
        }
    }
    sred[t] = bmax;
    __syncthreads();
    for (int s = 128; s > 0; s >>= 1) {
        if (t < s) sred[t] = fmaxf(sred[t], sred[t + s]);
        __syncthreads();
    }
    if (t == 0) atomicMax(&g_maxbits, __float_as_uint(sred[0]));
}

// ---------------- persistent Sinkhorn ----------------

struct SinkShared {
    float v[BATCH];          // 16 KB cached v
    float u[RPB];
    unsigned int sense;
    float red[32][CPB];
    float sh[16];
};

__device__ __forceinline__ void grid_bar(SinkShared* S) {
    __syncthreads();
    if (threadIdx.x == 0) {
        unsigned int target = S->sense ^ 1u;
        S->sense = target;
        __threadfence();
        unsigned int old = atomicAdd(&g_barcnt, 1u);
        if (old == NB - 1u) {
            g_barcnt = 0u;
            st_release(&g_barsense, target);
        } else {
            while (ld_acquire(&g_barsense) != target) { }
        }
    }
    __syncthreads();
}

__device__ __forceinline__ void load_v(SinkShared* S) {
    int t = threadIdx.x;
    float4* d = (float4*)S->v;
    const float4* s = (const float4*)g_v;
    d[t]       = s[t];
    d[t + 512] = s[t + 512];
    __syncthreads();
}

// col partials for this block's 16-row stripe: part[b][j] = sum_r u_r K[r][j]
template<bool FIRST>
__device__ __forceinline__ void phaseA(SinkShared* S, int b, int r0, float sc) {
    int t = threadIdx.x;
    float acc[8];
    #pragma unroll
    for (int j = 0; j < 8; j++) acc[j] = 0.0f;

    #pragma unroll
    for (int rb = 0; rb < RPB; rb += 4) {
        uint4 q[4];
        #pragma unroll
        for (int rr = 0; rr < 4; rr++)
            q[rr] = ((uint4*)(g_Kh + (size_t)(r0 + rb + rr) * BATCH))[t];
        #pragma unroll
        for (int rr = 0; rr < 4; rr++) {
            __nv_bfloat162* h = reinterpret_cast<__nv_bfloat162*>(&q[rr]);
            float f[8];
            #pragma unroll
            for (int j = 0; j < 4; j++) {
                float2 p = __bfloat1622float2(h[j]);
                f[2*j] = p.x; f[2*j+1] = p.y;
            }
            if (FIRST) {
                #pragma unroll
                for (int j = 0; j < 8; j++) f[j] = __expf(f[j] * sc);
                #pragma unroll
                for (int j = 0; j < 4; j++)
                    h[j] = __floats2bfloat162_rn(f[2*j], f[2*j+1]);
                ((uint4*)(g_Kh + (size_t)(r0 + rb + rr) * BATCH))[t] = q[rr];
                #pragma unroll
                for (int j = 0; j < 8; j++) acc[j] += f[j];
            } else {
                float ur = S->u[rb + rr];
                #pragma unroll
                for (int j = 0; j < 8; j++) acc[j] += ur * f[j];
            }
        }
    }
    if (FIRST) {
        #pragma unroll
        for (int j = 0; j < 8; j++) acc[j] *= INV_B;
    }
    float4* pp = (float4*)(g_part + (size_t)b * BATCH);
    pp[2*t + 0] = make_float4(acc[0], acc[1], acc[2], acc[3]);
    pp[2*t + 1] = make_float4(acc[4], acc[5], acc[6], acc[7]);
}

// reduce partials for this block's 16 cols. MODE 0: v = INV_B/s ; MODE 1: col = s * v
template<int MODE>
__device__ __forceinline__ void phaseB(SinkShared* S, int b) {
    int t = threadIdx.x;
    int c0 = b * CPB;
    int p  = t >> 4;
    int cl = t & 15;
    float s = 0.0f;
    #pragma unroll
    for (int i = 0; i < 8; i++)
        s += g_part[(size_t)(p + 32 * i) * BATCH + c0 + cl];
    S->red[p][cl] = s;
    __syncthreads();
    if (t < CPB) {
        float s2 = 0.0f;
        #pragma unroll
        for (int g = 0; g < 32; g++) s2 += S->red[g][t];
        if (MODE == 0) g_v[c0 + t] = INV_B / s2;
        else           g_col[c0 + t] = s2 * S->v[c0 + t];
    }
    __syncthreads();
}

// row dots: u_r = INV_B / dot(K[r,:], v) ; warp per row; v from smem
__device__ __forceinline__ void phaseC(SinkShared* S, int r0) {
    int warp = threadIdx.x >> 5, lane = threadIdx.x & 31;
    const uint4* row = (const uint4*)(g_Kh + (size_t)(r0 + warp) * BATCH);
    float s = 0.0f;
    #pragma unroll
    for (int i = 0; i < 16; i += 4) {
        uint4 q[4];
        #pragma unroll
        for (int j2 = 0; j2 < 4; j2++) q[j2] = row[lane + 32 * (i + j2)];
        #pragma unroll
        for (int j2 = 0; j2 < 4; j2++) {
            int slot = lane + 32 * (i + j2);
            const float4* vv = (const float4*)(S->v + 8 * slot);
            float4 va = vv[0], vb = vv[1];
            __nv_bfloat162* h = reinterpret_cast<__nv_bfloat162*>(&q[j2]);
            float2 f0 = __bfloat1622float2(h[0]);
            float2 f1 = __bfloat1622float2(h[1]);
            float2 f2 = __bfloat1622float2(h[2]);
            float2 f3 = __bfloat1622float2(h[3]);
            s += f0.x*va.x + f0.y*va.y + f1.x*va.z + f1.y*va.w
               + f2.x*vb.x + f2.y*vb.y + f3.x*vb.z + f3.y*vb.w;
        }
    }
    #pragma unroll
    for (int o = 16; o > 0; o >>= 1) s += __shfl_down_sync(0xffffffffu, s, o);
    if (lane == 0) S->u[warp] = INV_B / s;
    __syncthreads();
}

// row stats: se = sum exp(pi), rs = sum pi, ce = log(se) - pi_rr ; v from smem
__device__ __forceinline__ void phaseR(SinkShared* S, int r0) {
    int warp = threadIdx.x >> 5, lane = threadIdx.x & 31;
    int r = r0 + warp;
    float ur = S->u[warp];
    const uint4* row = (const uint4*)(g_Kh + (size_t)r * BATCH);
    float se = 0.0f, rs = 0.0f;
    #pragma unroll
    for (int i = 0; i < 16; i += 4) {
        uint4 q[4];
        #pragma unroll
        for (int j2 = 0; j2 < 4; j2++) q[j2] = row[lane + 32 * (i + j2)];
        #pragma unroll
        for (int j2 = 0; j2 < 4; j2++) {
            int slot = lane + 32 * (i + j2);
            const float4* vv = (const float4*)(S->v + 8 * slot);
            float4 va = vv[0], vb = vv[1];
            __nv_bfloat162* h = reinterpret_cast<__nv_bfloat162*>(&q[j2]);
            float2 f0 = __bfloat1622float2(h[0]);
            float2 f1 = __bfloat1622float2(h[1]);
            float2 f2 = __bfloat1622float2(h[2]);
            float2 f3 = __bfloat1622float2(h[3]);
            float p0 = ur * f0.x * va.x, p1 = ur * f0.y * va.y;
            float p2 = ur * f1.x * va.z, p3 = ur * f1.y * va.w;
            float p4 = ur * f2.x * vb.x, p5 = ur * f2.y * vb.y;
            float p6 = ur * f3.x * vb.z, p7 = ur * f3.y * vb.w;
            se += __expf(p0) + __expf(p1) + __expf(p2) + __expf(p3)
                + __expf(p4) + __expf(p5) + __expf(p6) + __expf(p7);
            rs += p0 + p1 + p2 + p3 + p4 + p5 + p6 + p7;
        }
    }
    #pragma unroll
    for (int o = 16; o > 0; o >>= 1) {
        se += __shfl_down_sync(0xffffffffu, se, o);
        rs += __shfl_down_sync(0xffffffffu, rs, o);
    }
    if (lane == 0) {
        float kd = __bfloat162float(g_Kh[(size_t)r * BATCH + r]);
        float diag = ur * kd * S->v[r];
        g_ce[r] = logf(se) - diag;
        g_rowsum[r] = rs;
    }
}

__global__ void __launch_bounds__(NT, 2) sink_persist_kernel(float* __restrict__ out) {
    __shared__ SinkShared S;
    int b = blockIdx.x;
    int t = threadIdx.x;
    int r0 = b * RPB;

    if (t == 0) S.sense = 0u;
    __syncthreads();

    float mx = __uint_as_float(g_maxbits);
    float sc = -1.0f / (EPS_W * mx);

    // iteration 0: exp fusion + col partials (u = INV_B), then v1
    phaseA<true>(&S, b, r0, sc);
    grid_bar(&S);
    phaseB<0>(&S, b);
    grid_bar(&S);

    // iterations 1..9
    for (int it = 1; it < NITER; it++) {
        load_v(&S);
        phaseC(&S, r0);
        phaseA<false>(&S, b, r0, sc);
        grid_bar(&S);
        phaseB<0>(&S, b);
        grid_bar(&S);
    }

    load_v(&S);
    phaseC(&S, r0);                // u_10 from v_10
    phaseA<false>(&S, b, r0, sc);  // partials with u_10
    grid_bar(&S);
    phaseB<1>(&S, b);              // g_col = colsum(pi)
    phaseR(&S, r0);                // row stats
    grid_bar(&S);

    if (b == 0) {
        float ce = 0.0f, klr = 0.0f, klc = 0.0f;
        for (int i = t; i < BATCH; i += NT) {
            ce += g_ce[i];
            float rs = g_rowsum[i];
            klr += rs * (logf(rs) - INV_B);
            float cs = g_col[i];
            klc += cs * (logf(cs) - INV_B);
        }
        float ce_t  = blockReduceSum512(ce,  S.sh);
        float klr_t = blockReduceSum512(klr, S.sh);
        float klc_t = blockReduceSum512(klc, S.sh);
        if (t == 0)
            out[0] = ce_t * INV_B + REG_W * (klc_t * INV_B + klr_t * INV_B);
    }
}

// ---------------- launcher ----------------
extern "C" void kernel_launch(void* const* d_in, const int* in_sizes, int n_in,
                              void* d_out, int out_size) {
    const float* audio = (const float*)d_in[0];
    const float* text  = (const float*)d_in[1];
    float* out = (float*)d_out;

    cudaFuncSetAttribute(gemm_mma_kernel,
                         cudaFuncAttributeMaxDynamicSharedMemorySize, GEMM_SMEM);

    init_kernel<<<1, 32>>>();
    normalize_kernel<<<2 * BATCH, 256>>>(audio, text);
    gemm_mma_kernel<<<dim3(BATCH / BN, BATCH / BM), 256, GEMM_SMEM>>>();
    sink_persist_kernel<<<NB, NT>>>(out);
}